// round 2
// baseline (speedup 1.0000x reference)
#include <cuda_runtime.h>
#include <math.h>
#include <float.h>
#include <stdint.h>

// Problem constants
#define DDIM 256
#define KCODE 1024
#define BATCH 16
#define HW 4096                  // 64*64
#define NPOS (BATCH * HW)        // 65536
#define ZQ_ELEMS (BATCH * DDIM * HW)  // 16777216

// Tiling
#define TN 64        // positions per CTA
#define TK 64        // emb rows per smem chunk
#define PZ 68        // z smem row pitch (floats), 16B-aligned rows
#define PE 257       // emb smem row pitch (floats), conflict-free strided reads

__device__ float  g_b[KCODE];
__device__ int    g_idx[NPOS];
__device__ double g_loss;

// ---------------------------------------------------------------------------
// Kernel: b_k = sum_d emb[k][d]^2 (one warp per k)
// ---------------------------------------------------------------------------
__global__ void k_bnorm(const float* __restrict__ emb) {
    int warp = blockIdx.x * (blockDim.x >> 5) + (threadIdx.x >> 5);
    int lane = threadIdx.x & 31;
    if (warp >= KCODE) return;
    const float* row = emb + (size_t)warp * DDIM;
    float s = 0.f;
    #pragma unroll
    for (int d = lane; d < DDIM; d += 32) { float v = row[d]; s = fmaf(v, v, s); }
    #pragma unroll
    for (int o = 16; o; o >>= 1) s += __shfl_xor_sync(0xffffffffu, s, o);
    if (lane == 0) g_b[warp] = s;
}

// ---------------------------------------------------------------------------
// Kernel: zero loss accumulator (must run every launch; graph replays it)
// ---------------------------------------------------------------------------
__global__ void k_init() { g_loss = 0.0; }

// ---------------------------------------------------------------------------
// Main kernel: per-position argmin over K codes.
// d(n,k) = fl( fl(a_n + b_k) - 2*c_nk ), c = dot(z_n, e_k), fp32 throughout,
// matching the reference's fp32 rounding structure. Tie-break: lowest k.
// Layout: 256 threads = 16(tx: k) x 16(ty: n). Thread computes 4n x 4k,
// n = ty*4+i (consecutive), k = tx + 16*j (strided; ascending over j).
// ---------------------------------------------------------------------------
extern __shared__ float smem_dyn[];

__global__ __launch_bounds__(256, 1)
void k_main(const float* __restrict__ z, const float* __restrict__ emb) {
    float* z_s = smem_dyn;                // [256][PZ]
    float* e_s = z_s + DDIM * PZ;         // [TK][PE]
    float* b_s = e_s + TK * PE;           // [1024]
    float* a_s = b_s + KCODE;             // [64]

    const int tid = threadIdx.x;
    const int tx = tid & 15;
    const int ty = tid >> 4;
    const int cta = blockIdx.x;           // 1024 CTAs, 64 consecutive n each
    const int bimg = cta >> 6;            // image index (4096/64 = 64 tiles/img)
    const int hw0  = (cta & 63) << 6;

    const float* zb = z + (size_t)bimg * DDIM * HW + hw0;

    // Load z tile [d][n] — NCHW is d-major so rows are coalesced.
    for (int i = tid; i < DDIM * TN; i += 256) {
        int d = i >> 6, n = i & 63;
        z_s[d * PZ + n] = zb[(size_t)d * HW + n];
    }
    for (int i = tid; i < KCODE; i += 256) b_s[i] = g_b[i];
    __syncthreads();

    // a_n = sum_d z^2, sequential ascending d (fp32)
    if (tid < TN) {
        float a = 0.f;
        for (int d = 0; d < DDIM; ++d) { float v = z_s[d * PZ + tid]; a = fmaf(v, v, a); }
        a_s[tid] = a;
    }
    __syncthreads();

    float av[4];
    #pragma unroll
    for (int i = 0; i < 4; ++i) av[i] = a_s[ty * 4 + i];

    float mind[4]; int mink[4];
    #pragma unroll
    for (int i = 0; i < 4; ++i) { mind[i] = FLT_MAX; mink[i] = 0; }

    const float* zp = z_s + ty * 4;

    for (int kb = 0; kb < KCODE; kb += TK) {
        __syncthreads();  // previous chunk fully consumed
        // Load emb chunk rows kb..kb+TK-1, natural [k][d] layout, coalesced.
        for (int i = tid; i < TK * DDIM; i += 256) {
            int kk = i >> 8, d = i & 255;
            e_s[kk * PE + d] = emb[(size_t)(kb + kk) * DDIM + d];
        }
        __syncthreads();

        float acc[4][4];
        #pragma unroll
        for (int i = 0; i < 4; ++i)
            #pragma unroll
            for (int j = 0; j < 4; ++j) acc[i][j] = 0.f;

        const float* ep0 = e_s + (tx +  0) * PE;
        const float* ep1 = e_s + (tx + 16) * PE;
        const float* ep2 = e_s + (tx + 32) * PE;
        const float* ep3 = e_s + (tx + 48) * PE;

        #pragma unroll 4
        for (int d = 0; d < DDIM; ++d) {
            float4 zv = *(const float4*)(zp + d * PZ);
            float ev0 = ep0[d], ev1 = ep1[d], ev2 = ep2[d], ev3 = ep3[d];
            const float zr[4] = {zv.x, zv.y, zv.z, zv.w};
            #pragma unroll
            for (int i = 0; i < 4; ++i) {
                acc[i][0] = fmaf(zr[i], ev0, acc[i][0]);
                acc[i][1] = fmaf(zr[i], ev1, acc[i][1]);
                acc[i][2] = fmaf(zr[i], ev2, acc[i][2]);
                acc[i][3] = fmaf(zr[i], ev3, acc[i][3]);
            }
        }

        // Compare: k ascending over j within the thread (tie -> earlier k kept)
        #pragma unroll
        for (int j = 0; j < 4; ++j) {
            int k = kb + tx + 16 * j;
            float bk = b_s[k];
            #pragma unroll
            for (int i = 0; i < 4; ++i) {
                float dv = fmaf(-2.0f, acc[i][j], av[i] + bk);
                if (dv < mind[i]) { mind[i] = dv; mink[i] = k; }
            }
        }
    }

    // Cross-lane argmin over the 16 tx lanes (lexicographic (d, k))
    #pragma unroll
    for (int i = 0; i < 4; ++i) {
        float v = mind[i]; int kk = mink[i];
        #pragma unroll
        for (int o = 8; o; o >>= 1) {
            float ov = __shfl_xor_sync(0xffffffffu, v, o, 16);
            int   ok = __shfl_xor_sync(0xffffffffu, kk, o, 16);
            if (ov < v || (ov == v && ok < kk)) { v = ov; kk = ok; }
        }
        if (tx == 0) {
            int n = (cta << 6) + ty * 4 + i;
            g_idx[n] = kk;
        }
    }
}

// ---------------------------------------------------------------------------
// Output + loss kernel: out[i] = z[i] + (e - z[i])  (straight-through rounding
// replicated exactly); loss sum accumulated via block reduce + double atomic.
// i is NCHW-linear -> coalesced; emb gather stays L2-resident (1 MB).
// ---------------------------------------------------------------------------
__global__ void k_out(const float* __restrict__ z, const float* __restrict__ emb,
                      float* __restrict__ out) {
    const long long total = (long long)ZQ_ELEMS;
    float local = 0.f;
    for (long long i = (long long)blockIdx.x * blockDim.x + threadIdx.x;
         i < total; i += (long long)gridDim.x * blockDim.x) {
        int b  = (int)(i >> 20);          // D*HW = 2^20
        int r  = (int)(i & 1048575);
        int d  = r >> 12;
        int hw = r & 4095;
        int n  = (b << 12) | hw;
        float e  = __ldg(&emb[(size_t)g_idx[n] * DDIM + d]);
        float zz = z[i];
        float diff = e - zz;              // also the loss term (z_q - sg(z))
        out[i] = zz + diff;               // straight-through value, exact rounding
        local = fmaf(diff, diff, local);
    }
    #pragma unroll
    for (int o = 16; o; o >>= 1) local += __shfl_xor_sync(0xffffffffu, local, o);
    __shared__ float ws[32];
    int lane = threadIdx.x & 31, w = threadIdx.x >> 5;
    if (lane == 0) ws[w] = local;
    __syncthreads();
    if (w == 0) {
        float s = (lane < (int)(blockDim.x >> 5)) ? ws[lane] : 0.f;
        #pragma unroll
        for (int o = 16; o; o >>= 1) s += __shfl_xor_sync(0xffffffffu, s, o);
        if (lane == 0) atomicAdd(&g_loss, (double)s);
    }
}

// ---------------------------------------------------------------------------
// Finalize: indices (as float) + loss scalar. All writes guarded by out_size.
// ---------------------------------------------------------------------------
__global__ void k_fin(float* __restrict__ out, long long out_size) {
    int i = blockIdx.x * blockDim.x + threadIdx.x;
    if (i < NPOS && (long long)ZQ_ELEMS + i < out_size)
        out[ZQ_ELEMS + i] = (float)g_idx[i];
    if (i == 0 && (long long)ZQ_ELEMS + NPOS < out_size)
        out[ZQ_ELEMS + NPOS] = (float)(0.25 * g_loss / (double)ZQ_ELEMS);
}

// ---------------------------------------------------------------------------
extern "C" void kernel_launch(void* const* d_in, const int* in_sizes, int n_in,
                              void* d_out, int out_size) {
    const float* z   = (const float*)d_in[0];   // [16,256,64,64] fp32
    const float* emb = (const float*)d_in[1];   // [1024,256] fp32
    float* out = (float*)d_out;

    const int smem_bytes = (DDIM * PZ + TK * PE + KCODE + TN) * (int)sizeof(float);
    // Idempotent host-side config; executed identically on every call.
    cudaFuncSetAttribute(k_main, cudaFuncAttributeMaxDynamicSharedMemorySize, smem_bytes);

    k_bnorm<<<KCODE / 8, 256>>>(emb);
    k_init<<<1, 1>>>();
    k_main<<<NPOS / TN, 256, smem_bytes>>>(z, emb);
    k_out<<<4096, 256>>>(z, emb, out);
    k_fin<<<(NPOS + 255) / 256, 256>>>(out, (long long)out_size);
}

// round 3
// speedup vs baseline: 1.2915x; 1.2915x over previous
#include <cuda_runtime.h>
#include <math.h>
#include <float.h>
#include <stdint.h>

// Problem constants
#define DDIM 256
#define KCODE 1024
#define HW 4096                  // 64*64
#define NPOS 65536               // 16 * 4096
#define ZQ_ELEMS 16777216        // 16 * 256 * 4096

// Main-kernel tiling
#define TN 64        // positions per CTA
#define CHUNK 64     // emb rows per smem chunk (double buffered)
#define NCHUNK (KCODE / CHUNK)   // 16
#define PZ 68        // z smem pitch (floats): 16B-aligned rows, warp-uniform reads
#define PE 257       // e smem pitch (floats): odd -> conflict-free strided reads

__device__ float  g_b[KCODE];
__device__ int    g_idx[NPOS];
__device__ double g_loss;

typedef unsigned long long ull;

// Packed fp32x2 helpers: fma.rn.f32x2 = two independent IEEE fp32 FMAs
// (bit-exact with two fmaf calls) at 2x FFMA throughput on sm_103a.
__device__ __forceinline__ ull pk2(float lo, float hi) {
    ull r; asm("mov.b64 %0, {%1, %2};" : "=l"(r) : "f"(lo), "f"(hi)); return r;
}
__device__ __forceinline__ void fma2(ull& acc, ull a, ull b) {
    asm("fma.rn.f32x2 %0, %1, %2, %0;" : "+l"(acc) : "l"(a), "l"(b));
}
__device__ __forceinline__ void upk2(ull v, float& lo, float& hi) {
    asm("mov.b64 {%0, %1}, %2;" : "=f"(lo), "=f"(hi) : "l"(v));
}

__device__ __forceinline__ unsigned smem_u32(const void* p) {
    return (unsigned)__cvta_generic_to_shared(p);
}
__device__ __forceinline__ void cp4(unsigned dst, const float* src) {
    asm volatile("cp.async.ca.shared.global [%0], [%1], 4;" :: "r"(dst), "l"(src));
}
__device__ __forceinline__ void cp_commit() { asm volatile("cp.async.commit_group;"); }
__device__ __forceinline__ void cp_wait0()  { asm volatile("cp.async.wait_group 0;"); }

// ---------------------------------------------------------------------------
// b_k = sum_d emb[k][d]^2 (one warp per k), sequential-equivalent fp32 order
// ---------------------------------------------------------------------------
__global__ void k_bnorm(const float* __restrict__ emb) {
    int warp = blockIdx.x * (blockDim.x >> 5) + (threadIdx.x >> 5);
    int lane = threadIdx.x & 31;
    if (warp >= KCODE) return;
    const float* row = emb + (size_t)warp * DDIM;
    float s = 0.f;
    #pragma unroll
    for (int d = lane; d < DDIM; d += 32) { float v = row[d]; s = fmaf(v, v, s); }
    #pragma unroll
    for (int o = 16; o; o >>= 1) s += __shfl_xor_sync(0xffffffffu, s, o);
    if (lane == 0) g_b[warp] = s;
}

__global__ void k_init() { g_loss = 0.0; }

// ---------------------------------------------------------------------------
// Main: per-position argmin over K codes, fp32x2 packed FMA GEMM core.
// Numerics identical to R2 (rel_err 0.0): each packed lane runs the same
// sequential-d fp32 fma chain; d(n,k) = fmaf(-2, c, a+b); tie -> lowest k.
// Thread layout: warp w (=ty) owns n in {4w..4w+3, 32+4w..32+4w+3} (8 n's,
// warp-uniform -> z smem reads are broadcasts). Lane tx owns k = kb+tx+32j.
// emb streamed in 64-row chunks, double buffered with cp.async.
// ---------------------------------------------------------------------------
extern __shared__ float smem_dyn[];

__global__ __launch_bounds__(256, 1)
void k_main(const float* __restrict__ z, const float* __restrict__ emb) {
    float* z_s  = smem_dyn;                    // [256][PZ]
    float* e_s0 = z_s  + DDIM * PZ;            // [CHUNK][PE]
    float* e_s1 = e_s0 + CHUNK * PE;           // [CHUNK][PE]
    float* b_s  = e_s1 + CHUNK * PE;           // [1024]
    float* a_s  = b_s + KCODE;                 // [64]

    const int tid = threadIdx.x;
    const int tx  = tid & 31;                  // lane: k dimension
    const int ty  = tid >> 5;                  // warp: n dimension (0..7)
    const int cta = blockIdx.x;                // 1024 CTAs x 64 n

    const int bimg = cta >> 6;
    const int hw0  = (cta & 63) << 6;
    const float* zb = z + (size_t)bimg * DDIM * HW + hw0;

    // Prefetch helper: chunk kb -> ebuf. Per warp: 8 rows; lanes cover d
    // contiguously (coalesced gmem, conflict-free smem at pitch 257).
    auto prefetch = [&](int kb, float* ebuf) {
        #pragma unroll
        for (int r = 0; r < 8; ++r) {
            int kk = ty * 8 + r;
            const float* src = emb + (size_t)(kb + kk) * DDIM + tx;
            unsigned dst = smem_u32(ebuf + kk * PE + tx);
            #pragma unroll
            for (int s = 0; s < 8; ++s) cp4(dst + s * 128, src + s * 32);
        }
    };

    // Load z tile [d][n] (float4 both sides), b_s; prefetch chunk 0.
    for (int i = tid; i < DDIM * (TN / 4); i += 256) {
        int d = i >> 4, q4 = (i & 15) << 2;
        *(float4*)(z_s + d * PZ + q4) = *(const float4*)(zb + (size_t)d * HW + q4);
    }
    for (int i = tid; i < KCODE; i += 256) b_s[i] = g_b[i];
    prefetch(0, e_s0);
    cp_commit();
    cp_wait0();
    __syncthreads();                            // z_s, b_s, chunk0 visible

    // a_n = sum_d z^2 (sequential d, same order as R2); prefetch chunk 1.
    if (tid < TN) {
        float a = 0.f;
        for (int d = 0; d < DDIM; ++d) { float v = z_s[d * PZ + tid]; a = fmaf(v, v, a); }
        a_s[tid] = a;
    }
    prefetch(CHUNK, e_s1);
    cp_commit();
    __syncthreads();                            // a_s visible (chunk1 waited later)

    float av[8];
    #pragma unroll
    for (int i = 0; i < 8; ++i) {
        int nloc = ((i >> 2) << 5) + (ty << 2) + (i & 3);   // {4ty+q, 32+4ty+q}
        av[i] = a_s[nloc];
    }

    float mind[8]; int mink[8];
    #pragma unroll
    for (int i = 0; i < 8; ++i) { mind[i] = FLT_MAX; mink[i] = 0; }

    const float* zbase = z_s + (ty << 2);

    for (int c = 0; c < NCHUNK; ++c) {
        const float* ebuf = (c & 1) ? e_s1 : e_s0;
        const float* ep0 = ebuf + tx * PE;          // k = kb + tx
        const float* ep1 = ebuf + (tx + 32) * PE;   // k = kb + tx + 32
        const float* zp  = zbase;

        ull acc[4][2];
        #pragma unroll
        for (int p = 0; p < 4; ++p) { acc[p][0] = 0ull; acc[p][1] = 0ull; }

        #pragma unroll 4
        for (int d = 0; d < DDIM; ++d) {
            float4 zA = *(const float4*)(zp);        // n = 4ty..4ty+3 (broadcast)
            float4 zB = *(const float4*)(zp + 32);   // n = 32+4ty..32+4ty+3
            float e0 = ep0[0], e1 = ep1[0];
            ull E0 = pk2(e0, e0), E1 = pk2(e1, e1);
            ull Z0 = pk2(zA.x, zA.y), Z1 = pk2(zA.z, zA.w);
            ull Z2 = pk2(zB.x, zB.y), Z3 = pk2(zB.z, zB.w);
            fma2(acc[0][0], Z0, E0); fma2(acc[1][0], Z1, E0);
            fma2(acc[2][0], Z2, E0); fma2(acc[3][0], Z3, E0);
            fma2(acc[0][1], Z0, E1); fma2(acc[1][1], Z1, E1);
            fma2(acc[2][1], Z2, E1); fma2(acc[3][1], Z3, E1);
            zp += PZ; ++ep0; ++ep1;
        }

        // Compare: j ascending -> k ascending within lane (tie keeps lower k)
        int kb = c * CHUNK;
        #pragma unroll
        for (int j = 0; j < 2; ++j) {
            int k = kb + tx + (j << 5);
            float bk = b_s[k];
            #pragma unroll
            for (int p = 0; p < 4; ++p) {
                float lo, hi; upk2(acc[p][j], lo, hi);
                int i0 = ((p >> 1) << 2) + ((p & 1) << 1);   // av/min slot of pair lo
                float dv0 = fmaf(-2.0f, lo, av[i0]     + bk);
                float dv1 = fmaf(-2.0f, hi, av[i0 + 1] + bk);
                if (dv0 < mind[i0])     { mind[i0]     = dv0; mink[i0]     = k; }
                if (dv1 < mind[i0 + 1]) { mind[i0 + 1] = dv1; mink[i0 + 1] = k; }
            }
        }

        if (c + 1 < NCHUNK) {
            cp_wait0();
            __syncthreads();     // chunk c+1 ready; all reads of buf[c&1] done
            if (c + 2 < NCHUNK) {
                prefetch((c + 2) * CHUNK, (c & 1) ? e_s1 : e_s0);
                cp_commit();
            }
        }
    }

    // Cross-lane argmin over 32 lanes (lexicographic (d, k)), lane 0 writes.
    #pragma unroll
    for (int i = 0; i < 8; ++i) {
        float v = mind[i]; int kk = mink[i];
        #pragma unroll
        for (int o = 16; o; o >>= 1) {
            float ov = __shfl_xor_sync(0xffffffffu, v, o);
            int   ok = __shfl_xor_sync(0xffffffffu, kk, o);
            if (ov < v || (ov == v && ok < kk)) { v = ov; kk = ok; }
        }
        if (tx == 0) {
            int nloc = ((i >> 2) << 5) + (ty << 2) + (i & 3);
            g_idx[(cta << 6) + nloc] = kk;
        }
    }
}

// ---------------------------------------------------------------------------
// Output + loss: thread handles 4 consecutive d for one n -> 1 idx load and
// 1 float4 emb gather per 4 elements (was 1 each per element: L1-bound).
// ---------------------------------------------------------------------------
__global__ void k_out(const float* __restrict__ z, const float* __restrict__ emb,
                      float* __restrict__ out) {
    const int nitems = NPOS * 64;              // n x (d/4)
    float local = 0.f;
    for (int item = blockIdx.x * blockDim.x + threadIdx.x;
         item < nitems; item += gridDim.x * blockDim.x) {
        int n  = item & (NPOS - 1);
        int dq = item >> 16;
        int idx = __ldg(&g_idx[n]);
        float4 e4 = *(const float4*)(emb + (size_t)idx * DDIM + (dq << 2));
        int b = n >> 12, hw = n & 4095;
        size_t base = ((size_t)b << 20) + ((size_t)(dq << 2) << 12) + hw;
        float ev[4] = {e4.x, e4.y, e4.z, e4.w};
        #pragma unroll
        for (int q = 0; q < 4; ++q) {
            size_t a = base + ((size_t)q << 12);
            float zz = z[a];
            float diff = ev[q] - zz;
            out[a] = zz + diff;                 // straight-through, exact rounding
            local = fmaf(diff, diff, local);
        }
    }
    #pragma unroll
    for (int o = 16; o; o >>= 1) local += __shfl_xor_sync(0xffffffffu, local, o);
    __shared__ float ws[32];
    int lane = threadIdx.x & 31, w = threadIdx.x >> 5;
    if (lane == 0) ws[w] = local;
    __syncthreads();
    if (w == 0) {
        float s = (lane < (int)(blockDim.x >> 5)) ? ws[lane] : 0.f;
        #pragma unroll
        for (int o = 16; o; o >>= 1) s += __shfl_xor_sync(0xffffffffu, s, o);
        if (lane == 0) atomicAdd(&g_loss, (double)s);
    }
}

// ---------------------------------------------------------------------------
__global__ void k_fin(float* __restrict__ out, long long out_size) {
    int i = blockIdx.x * blockDim.x + threadIdx.x;
    if (i < NPOS && (long long)ZQ_ELEMS + i < out_size)
        out[ZQ_ELEMS + i] = (float)g_idx[i];
    if (i == 0 && (long long)ZQ_ELEMS + NPOS < out_size)
        out[ZQ_ELEMS + NPOS] = (float)(0.25 * g_loss / (double)ZQ_ELEMS);
}

// ---------------------------------------------------------------------------
extern "C" void kernel_launch(void* const* d_in, const int* in_sizes, int n_in,
                              void* d_out, int out_size) {
    const float* z   = (const float*)d_in[0];   // [16,256,64,64] fp32
    const float* emb = (const float*)d_in[1];   // [1024,256] fp32
    float* out = (float*)d_out;

    const int smem_bytes =
        (DDIM * PZ + 2 * CHUNK * PE + KCODE + TN) * (int)sizeof(float); // 205,568 B
    cudaFuncSetAttribute(k_main, cudaFuncAttributeMaxDynamicSharedMemorySize, smem_bytes);

    k_bnorm<<<KCODE / 8, 256>>>(emb);
    k_init<<<1, 1>>>();
    k_main<<<NPOS / TN, 256, smem_bytes>>>(z, emb);
    k_out<<<2048, 256>>>(z, emb, out);
    k_fin<<<(NPOS + 255) / 256, 256>>>(out, (long long)out_size);
}

// round 5
// speedup vs baseline: 2.1517x; 1.6660x over previous
#include <cuda_runtime.h>
#include <cuda_bf16.h>
#include <math.h>
#include <float.h>
#include <stdint.h>

// Problem constants
#define DDIM 256
#define KCODE 1024
#define HW 4096
#define NPOS 65536
#define ZQ_ELEMS 16777216

// Screening margin: reference's final subtract quantizes dv on a grid of
// ulp(~256)=3.05e-5; bf16-split TC dot error ~1e-6 << grid. Gap > 2 grid
// steps + slack  =>  argmin provably identical to the reference's.
#define DELTA_GAP 8e-5f

__device__ float  g_b[KCODE];
__device__ float  g_a[NPOS];
__device__ int    g_idx[NPOS];
__device__ int    g_flag[NPOS];
__device__ int    g_cnt;
__device__ double g_loss;
__device__ __align__(16) __nv_bfloat16 g_zh[(size_t)NPOS * DDIM];
__device__ __align__(16) __nv_bfloat16 g_zl[(size_t)NPOS * DDIM];
__device__ __align__(16) __nv_bfloat16 g_eh[KCODE * DDIM];
__device__ __align__(16) __nv_bfloat16 g_el[KCODE * DDIM];

// ---------------------------------------------------------------------------
// PTX helpers — all sm_80-class features, valid on plain sm_103 target
// ---------------------------------------------------------------------------
__device__ __forceinline__ unsigned stu32(const void* p) {
    return (unsigned)__cvta_generic_to_shared(p);
}
__device__ __forceinline__ void cp16(unsigned dst, const void* src) {
    asm volatile("cp.async.cg.shared.global [%0], [%1], 16;" :: "r"(dst), "l"(src));
}
__device__ __forceinline__ void cp_commit() { asm volatile("cp.async.commit_group;"); }
__device__ __forceinline__ void cp_wait1()  { asm volatile("cp.async.wait_group 1;"); }
__device__ __forceinline__ void cp_wait0()  { asm volatile("cp.async.wait_group 0;"); }

__device__ __forceinline__ void ldm4(unsigned* r, unsigned addr) {
    asm volatile("ldmatrix.sync.aligned.m8n8.x4.shared.b16 {%0,%1,%2,%3}, [%4];"
        : "=r"(r[0]), "=r"(r[1]), "=r"(r[2]), "=r"(r[3]) : "r"(addr));
}
__device__ __forceinline__ void mma16816(float* c, const unsigned* a,
                                         unsigned b0, unsigned b1) {
    asm volatile(
        "mma.sync.aligned.m16n8k16.row.col.f32.bf16.bf16.f32 "
        "{%0,%1,%2,%3}, {%4,%5,%6,%7}, {%8,%9}, {%0,%1,%2,%3};"
        : "+f"(c[0]), "+f"(c[1]), "+f"(c[2]), "+f"(c[3])
        : "r"(a[0]), "r"(a[1]), "r"(a[2]), "r"(a[3]), "r"(b0), "r"(b1));
}

// ---------------------------------------------------------------------------
// emb prep: exact b_k (same order as the rel_err=0.0 R2/R3 kernels) + bf16 split
// ---------------------------------------------------------------------------
__global__ void k_prep(const float* __restrict__ emb) {
    int warp = blockIdx.x * (blockDim.x >> 5) + (threadIdx.x >> 5);
    int lane = threadIdx.x & 31;
    if (warp >= KCODE) return;
    const float* row = emb + (size_t)warp * DDIM;
    float s = 0.f;
    #pragma unroll
    for (int d = lane; d < DDIM; d += 32) { float v = row[d]; s = fmaf(v, v, s); }
    #pragma unroll
    for (int o = 16; o; o >>= 1) s += __shfl_xor_sync(0xffffffffu, s, o);
    if (lane == 0) g_b[warp] = s;

    __align__(16) __nv_bfloat16 h[8], l[8];
    int base = lane * 8;
    #pragma unroll
    for (int q = 0; q < 8; ++q) {
        float v = row[base + q];
        h[q] = __float2bfloat16(v);
        l[q] = __float2bfloat16(v - __bfloat162float(h[q]));
    }
    *reinterpret_cast<uint4*>(&g_eh[warp * DDIM + base]) = *reinterpret_cast<uint4*>(h);
    *reinterpret_cast<uint4*>(&g_el[warp * DDIM + base]) = *reinterpret_cast<uint4*>(l);
}

__global__ void k_init() { g_loss = 0.0; g_cnt = 0; }

// ---------------------------------------------------------------------------
// z split + a_n: transpose NCHW -> [n][d] bf16 hi/lo; a_n exact sequential-d.
// ---------------------------------------------------------------------------
__global__ __launch_bounds__(256)
void k_split(const float* __restrict__ z) {
    __shared__ float s[64 * 129];
    int n0 = blockIdx.x * 128;
    int b = n0 >> 12, hw0 = n0 & 4095;
    const float* zb = z + ((size_t)b << 20) + hw0;
    int t = threadIdx.x;
    float a = 0.f;
    int nn = t >> 1, hf = t & 1;

    for (int c = 0; c < 4; ++c) {
        int d0 = c * 64;
        __syncthreads();
        for (int i = t; i < 64 * 128; i += 256) {
            int d = i >> 7, hw = i & 127;
            s[d * 129 + hw] = zb[(size_t)(d0 + d) * HW + hw];
        }
        __syncthreads();
        __align__(16) __nv_bfloat16 hh[32], ll[32];
        #pragma unroll
        for (int dd = 0; dd < 32; ++dd) {
            float v = s[(hf * 32 + dd) * 129 + nn];
            hh[dd] = __float2bfloat16(v);
            ll[dd] = __float2bfloat16(v - __bfloat162float(hh[dd]));
        }
        size_t off = (size_t)(n0 + nn) * DDIM + d0 + hf * 32;
        #pragma unroll
        for (int q = 0; q < 4; ++q) {
            *reinterpret_cast<uint4*>(&g_zh[off + q * 8]) = *reinterpret_cast<uint4*>(hh + q * 8);
            *reinterpret_cast<uint4*>(&g_zl[off + q * 8]) = *reinterpret_cast<uint4*>(ll + q * 8);
        }
        if (t < 128) {
            #pragma unroll 4
            for (int dd = 0; dd < 64; ++dd) { float v = s[dd * 129 + t]; a = fmaf(v, v, a); }
        }
    }
    if (t < 128) g_a[n0 + t] = a;
}

// ---------------------------------------------------------------------------
// HMMA screening kernel: CTA = 128 n x all 1024 codes.
// 8 warps, warp w owns rows w*16..w*16+15; K swept in 32-code chunks
// (double-buffered cp.async). c = zh*eh + zh*el + zl*eh in one fp32 HMMA acc.
// Per n: track (min1, k1, min2); gap <= DELTA_GAP -> flag for exact fallback.
// smem pitch: 264 bf16 = 528 B rows (odd x 16B -> ldmatrix conflict-free).
// ---------------------------------------------------------------------------
#define PD 264
#define ROWB 528
#define OFF_AH 0
#define OFF_AL 67584            /* 128*528 */
#define OFF_B  135168           /* 2 bufs x (Bh 16896 + Bl 16896) */
#define OFF_BS 202752           /* 1024 floats */
#define OFF_AS 206848           /* 128 floats */
#define SM_TOTAL 207360

extern __shared__ char sm_raw[];

__global__ void __launch_bounds__(256, 1)
k_mma() {
    unsigned sb = stu32(sm_raw);
    const int tid = threadIdx.x;
    const int lane = tid & 31, w = tid >> 5;         // w = n-tile 0..7
    const int n0 = blockIdx.x * 128;

    // Load A (z rows n0..n0+127, hi+lo) via cp.async
    {
        const char* zh = (const char*)g_zh;
        const char* zl = (const char*)g_zl;
        for (int u = tid; u < 128 * 32; u += 256) {
            int r = u >> 5, j = u & 31;
            size_t src = (size_t)(n0 + r) * 512 + j * 16;
            unsigned dst = r * ROWB + j * 16;
            cp16(sb + OFF_AH + dst, zh + src);
            cp16(sb + OFF_AL + dst, zl + src);
        }
    }
    auto prefB = [&](int c) {
        unsigned bufh = sb + OFF_B + (c & 1) * 33792;
        const char* eh = (const char*)g_eh;
        const char* el = (const char*)g_el;
        for (int u = tid; u < 32 * 32; u += 256) {
            int r = u >> 5, j = u & 31;
            size_t src = (size_t)(c * 32 + r) * 512 + j * 16;
            unsigned dst = r * ROWB + j * 16;
            cp16(bufh + dst, eh + src);
            cp16(bufh + 16896 + dst, el + src);
        }
    };
    prefB(0); cp_commit();      // G0 = A + B(0)
    prefB(1); cp_commit();      // G1 = B(1)

    float* bsm  = (float*)(sm_raw + OFF_BS);
    float* asm_ = (float*)(sm_raw + OFF_AS);
    for (int i = tid; i < KCODE; i += 256) bsm[i] = g_b[i];
    if (tid < 128) asm_[tid] = g_a[n0 + tid];
    __syncthreads();

    // Per-lane ldmatrix addresses (x4 = 4 8x8 matrices)
    const int grp = lane >> 3, ii = lane & 7;
    // A: m0 rows0-7/d0-7, m1 rows8-15/d0-7, m2 rows0-7/d8-15, m3 rows8-15/d8-15
    const unsigned aOff = (unsigned)((w * 16 + ((grp & 1) ? 8 : 0) + ii) * ROWB
                                     + ((grp & 2) ? 16 : 0));
    // B: m0 codes0-7/d0-7, m1 codes0-7/d8-15, m2 codes8-15/d0-7, m3 codes8-15/d8-15
    const unsigned bOff = (unsigned)((((grp >> 1) ? 8 : 0) + ii) * ROWB
                                     + ((grp & 1) ? 16 : 0));

    const float aA = asm_[w * 16 + (lane >> 2)];
    const float aB = asm_[w * 16 + (lane >> 2) + 8];
    float m1A = FLT_MAX, m2A = FLT_MAX, m1B = FLT_MAX, m2B = FLT_MAX;
    int k1A = 0, k1B = 0;

    #define UPD(m1, m2, k1, dv, k) \
        { if ((dv) < (m1)) { (m2) = (m1); (m1) = (dv); (k1) = (k); } \
          else if ((dv) < (m2)) (m2) = (dv); }

    for (int c = 0; c < 32; ++c) {
        if (c == 31) cp_wait0(); else cp_wait1();   // B(c) resident
        __syncthreads();

        unsigned bufh = sb + OFF_B + (c & 1) * 33792;
        unsigned pAh = sb + OFF_AH + aOff;
        unsigned pAl = sb + OFF_AL + aOff;
        unsigned pH0 = bufh + bOff;                  // codes 0-15
        unsigned pH1 = bufh + 16 * ROWB + bOff;      // codes 16-31
        unsigned pL0 = bufh + 16896 + bOff;
        unsigned pL1 = bufh + 16896 + 16 * ROWB + bOff;

        float C[4][4];
        #pragma unroll
        for (int t = 0; t < 4; ++t)
            #pragma unroll
            for (int q = 0; q < 4; ++q) C[t][q] = 0.f;

        #pragma unroll 4
        for (int s = 0; s < 16; ++s) {
            unsigned Ah[4], Al[4], B0[4], B1[4], B2[4], B3[4];
            ldm4(Ah, pAh); ldm4(Al, pAl);
            ldm4(B0, pH0); ldm4(B1, pH1);
            ldm4(B2, pL0); ldm4(B3, pL1);
            // zh*eh
            mma16816(C[0], Ah, B0[0], B0[1]);
            mma16816(C[1], Ah, B0[2], B0[3]);
            mma16816(C[2], Ah, B1[0], B1[1]);
            mma16816(C[3], Ah, B1[2], B1[3]);
            // zh*el
            mma16816(C[0], Ah, B2[0], B2[1]);
            mma16816(C[1], Ah, B2[2], B2[3]);
            mma16816(C[2], Ah, B3[0], B3[1]);
            mma16816(C[3], Ah, B3[2], B3[3]);
            // zl*eh
            mma16816(C[0], Al, B0[0], B0[1]);
            mma16816(C[1], Al, B0[2], B0[3]);
            mma16816(C[2], Al, B1[0], B1[1]);
            mma16816(C[3], Al, B1[2], B1[3]);
            pAh += 32; pAl += 32; pH0 += 32; pH1 += 32; pL0 += 32; pL1 += 32;
        }

        int kb = c * 32 + (lane & 3) * 2;
        #pragma unroll
        for (int t = 0; t < 4; ++t) {
            int kc = kb + t * 8;
            float b0 = bsm[kc], b1 = bsm[kc + 1];
            float d0 = fmaf(-2.f, C[t][0], aA + b0);
            float d1 = fmaf(-2.f, C[t][1], aA + b1);
            float d2 = fmaf(-2.f, C[t][2], aB + b0);
            float d3 = fmaf(-2.f, C[t][3], aB + b1);
            UPD(m1A, m2A, k1A, d0, kc);
            UPD(m1A, m2A, k1A, d1, kc + 1);
            UPD(m1B, m2B, k1B, d2, kc);
            UPD(m1B, m2B, k1B, d3, kc + 1);
        }

        __syncthreads();                             // all warps done with buf
        if (c + 2 < 32) { prefB(c + 2); cp_commit(); }
    }

    // Reduce across the 4 lanes sharing each row (lex (dv,k); true 2nd-min)
    #pragma unroll
    for (int o = 1; o <= 2; o <<= 1) {
        float om1 = __shfl_xor_sync(0xffffffffu, m1A, o);
        int   ok1 = __shfl_xor_sync(0xffffffffu, k1A, o);
        float om2 = __shfl_xor_sync(0xffffffffu, m2A, o);
        bool take = (om1 < m1A) || (om1 == m1A && ok1 < k1A);
        m2A = fminf(fminf(m2A, om2), take ? m1A : om1);
        if (take) { m1A = om1; k1A = ok1; }

        om1 = __shfl_xor_sync(0xffffffffu, m1B, o);
        ok1 = __shfl_xor_sync(0xffffffffu, k1B, o);
        om2 = __shfl_xor_sync(0xffffffffu, m2B, o);
        take = (om1 < m1B) || (om1 == m1B && ok1 < k1B);
        m2B = fminf(fminf(m2B, om2), take ? m1B : om1);
        if (take) { m1B = om1; k1B = ok1; }
    }
    if ((lane & 3) == 0) {
        int nA = n0 + w * 16 + (lane >> 2);
        if (m2A - m1A > DELTA_GAP) g_idx[nA] = k1A;
        else g_flag[atomicAdd(&g_cnt, 1)] = nA;
        int nB = nA + 8;
        if (m2B - m1B > DELTA_GAP) g_idx[nB] = k1B;
        else g_flag[atomicAdd(&g_cnt, 1)] = nB;
    }
}

// ---------------------------------------------------------------------------
// Exact fallback: bit-identical fp32 full scan for flagged positions only.
// ---------------------------------------------------------------------------
__global__ __launch_bounds__(256)
void k_exact(const float* __restrict__ z, const float* __restrict__ emb) {
    __shared__ float zs[8][257];
    __shared__ float es[32][257];
    __shared__ int ns[8];
    __shared__ float aa[8];
    int tx = threadIdx.x & 31, ty = threadIdx.x >> 5;

    for (int base = blockIdx.x * 8; base < g_cnt; base += gridDim.x * 8) {
        int cnt = g_cnt;
        if (threadIdx.x < 8) {
            int v = (base + threadIdx.x < cnt) ? g_flag[base + threadIdx.x] : -1;
            ns[threadIdx.x] = v;
            aa[threadIdx.x] = (v >= 0) ? g_a[v] : 0.f;
        }
        __syncthreads();
        for (int i = threadIdx.x; i < 8 * 256; i += 256) {
            int sl = i >> 8, d = i & 255;
            int nn = ns[sl];
            zs[sl][d] = (nn >= 0)
                ? z[((size_t)(nn >> 12) << 20) + ((size_t)d << 12) + (nn & 4095)] : 0.f;
        }
        float m1 = FLT_MAX; int k1 = 0;
        for (int c0 = 0; c0 < KCODE; c0 += 32) {
            __syncthreads();
            for (int i = threadIdx.x; i < 32 * 256; i += 256) {
                int r = i >> 8, d = i & 255;
                es[r][d] = emb[(size_t)(c0 + r) * DDIM + d];
            }
            __syncthreads();
            float c = 0.f;
            const float* zr = zs[ty];
            const float* er = es[tx];
            #pragma unroll 4
            for (int d = 0; d < DDIM; ++d) c = fmaf(zr[d], er[d], c);
            float dv = fmaf(-2.0f, c, aa[ty] + g_b[c0 + tx]);
            if (dv < m1) { m1 = dv; k1 = c0 + tx; }
        }
        #pragma unroll
        for (int o = 16; o; o >>= 1) {
            float ov = __shfl_xor_sync(0xffffffffu, m1, o);
            int   ok = __shfl_xor_sync(0xffffffffu, k1, o);
            if (ov < m1 || (ov == m1 && ok < k1)) { m1 = ov; k1 = ok; }
        }
        if (tx == 0 && ns[ty] >= 0) g_idx[ns[ty]] = k1;
        __syncthreads();
    }
}

// ---------------------------------------------------------------------------
// Output + loss (proven in R3)
// ---------------------------------------------------------------------------
__global__ void k_out(const float* __restrict__ z, const float* __restrict__ emb,
                      float* __restrict__ out) {
    const int nitems = NPOS * 64;
    float local = 0.f;
    for (int item = blockIdx.x * blockDim.x + threadIdx.x;
         item < nitems; item += gridDim.x * blockDim.x) {
        int n  = item & (NPOS - 1);
        int dq = item >> 16;
        int idx = __ldg(&g_idx[n]);
        float4 e4 = *(const float4*)(emb + (size_t)idx * DDIM + (dq << 2));
        int b = n >> 12, hw = n & 4095;
        size_t base = ((size_t)b << 20) + ((size_t)(dq << 2) << 12) + hw;
        float ev[4] = {e4.x, e4.y, e4.z, e4.w};
        #pragma unroll
        for (int q = 0; q < 4; ++q) {
            size_t a = base + ((size_t)q << 12);
            float zz = z[a];
            float diff = ev[q] - zz;
            out[a] = zz + diff;
            local = fmaf(diff, diff, local);
        }
    }
    #pragma unroll
    for (int o = 16; o; o >>= 1) local += __shfl_xor_sync(0xffffffffu, local, o);
    __shared__ float ws[32];
    int lane = threadIdx.x & 31, w = threadIdx.x >> 5;
    if (lane == 0) ws[w] = local;
    __syncthreads();
    if (w == 0) {
        float s = (lane < (int)(blockDim.x >> 5)) ? ws[lane] : 0.f;
        #pragma unroll
        for (int o = 16; o; o >>= 1) s += __shfl_xor_sync(0xffffffffu, s, o);
        if (lane == 0) atomicAdd(&g_loss, (double)s);
    }
}

__global__ void k_fin(float* __restrict__ out, long long out_size) {
    int i = blockIdx.x * blockDim.x + threadIdx.x;
    if (i < NPOS && (long long)ZQ_ELEMS + i < out_size)
        out[ZQ_ELEMS + i] = (float)g_idx[i];
    if (i == 0 && (long long)ZQ_ELEMS + NPOS < out_size)
        out[ZQ_ELEMS + NPOS] = (float)(0.25 * g_loss / (double)ZQ_ELEMS);
}

// ---------------------------------------------------------------------------
extern "C" void kernel_launch(void* const* d_in, const int* in_sizes, int n_in,
                              void* d_out, int out_size) {
    const float* z   = (const float*)d_in[0];
    const float* emb = (const float*)d_in[1];
    float* out = (float*)d_out;

    cudaFuncSetAttribute(k_mma, cudaFuncAttributeMaxDynamicSharedMemorySize, SM_TOTAL);

    k_prep<<<KCODE / 8, 256>>>(emb);
    k_init<<<1, 1>>>();
    k_split<<<NPOS / 128, 256>>>(z);
    k_mma<<<NPOS / 128, 256, SM_TOTAL>>>();
    k_exact<<<256, 256>>>(z, emb);
    k_out<<<2048, 256>>>(z, emb, out);
    k_fin<<<(NPOS + 255) / 256, 256>>>(out, (long long)out_size);
}

// round 6
// speedup vs baseline: 2.4090x; 1.1196x over previous
#include <cuda_runtime.h>
#include <cuda_bf16.h>
#include <math.h>
#include <float.h>
#include <stdint.h>

// Problem constants
#define DDIM 256
#define KCODE 1024
#define HW 4096
#define NPOS 65536
#define ZQ_ELEMS 16777216

// Screening margin: reference's final subtract quantizes dv on a grid of
// ulp(~256)=3.05e-5; bf16-split TC dot error ~1e-7..1e-6 << grid. Gap > 2 grid
// steps + slack  =>  argmin provably identical to the reference's.
#define DELTA_GAP 8e-5f

__device__ float  g_b[KCODE];
__device__ float  g_a[NPOS];
__device__ int    g_idx[NPOS];
__device__ int    g_flag[NPOS];
__device__ int    g_cnt;
__device__ double g_loss;
__device__ __align__(16) __nv_bfloat16 g_eh[KCODE * DDIM];
__device__ __align__(16) __nv_bfloat16 g_el[KCODE * DDIM];

// ---------------------------------------------------------------------------
// PTX helpers — all sm_80-class features, valid on plain sm_103 target
// ---------------------------------------------------------------------------
__device__ __forceinline__ unsigned stu32(const void* p) {
    return (unsigned)__cvta_generic_to_shared(p);
}
__device__ __forceinline__ void cp16(unsigned dst, const void* src) {
    asm volatile("cp.async.cg.shared.global [%0], [%1], 16;" :: "r"(dst), "l"(src));
}
__device__ __forceinline__ void cp_commit() { asm volatile("cp.async.commit_group;"); }
__device__ __forceinline__ void cp_wait1()  { asm volatile("cp.async.wait_group 1;"); }
__device__ __forceinline__ void cp_wait0()  { asm volatile("cp.async.wait_group 0;"); }

__device__ __forceinline__ void ldm4(unsigned* r, unsigned addr) {
    asm volatile("ldmatrix.sync.aligned.m8n8.x4.shared.b16 {%0,%1,%2,%3}, [%4];"
        : "=r"(r[0]), "=r"(r[1]), "=r"(r[2]), "=r"(r[3]) : "r"(addr));
}
__device__ __forceinline__ void mma16816(float* c, const unsigned* a,
                                         unsigned b0, unsigned b1) {
    asm volatile(
        "mma.sync.aligned.m16n8k16.row.col.f32.bf16.bf16.f32 "
        "{%0,%1,%2,%3}, {%4,%5,%6,%7}, {%8,%9}, {%0,%1,%2,%3};"
        : "+f"(c[0]), "+f"(c[1]), "+f"(c[2]), "+f"(c[3])
        : "r"(a[0]), "r"(a[1]), "r"(a[2]), "r"(a[3]), "r"(b0), "r"(b1));
}

// ---------------------------------------------------------------------------
// emb prep: exact b_k (same order as the rel_err=0.0 kernels) + bf16 split.
// Also zeroes the loss/flag accumulators (replay-safe).
// ---------------------------------------------------------------------------
__global__ void k_prep(const float* __restrict__ emb) {
    if (blockIdx.x == 0 && threadIdx.x == 0) { g_loss = 0.0; g_cnt = 0; }
    int warp = blockIdx.x * (blockDim.x >> 5) + (threadIdx.x >> 5);
    int lane = threadIdx.x & 31;
    if (warp >= KCODE) return;
    const float* row = emb + (size_t)warp * DDIM;
    float s = 0.f;
    #pragma unroll
    for (int d = lane; d < DDIM; d += 32) { float v = row[d]; s = fmaf(v, v, s); }
    #pragma unroll
    for (int o = 16; o; o >>= 1) s += __shfl_xor_sync(0xffffffffu, s, o);
    if (lane == 0) g_b[warp] = s;

    __align__(16) __nv_bfloat16 h[8], l[8];
    int base = lane * 8;
    #pragma unroll
    for (int q = 0; q < 8; ++q) {
        float v = row[base + q];
        h[q] = __float2bfloat16(v);
        l[q] = __float2bfloat16(v - __bfloat162float(h[q]));
    }
    *reinterpret_cast<uint4*>(&g_eh[warp * DDIM + base]) = *reinterpret_cast<uint4*>(h);
    *reinterpret_cast<uint4*>(&g_el[warp * DDIM + base]) = *reinterpret_cast<uint4*>(l);
}

// ---------------------------------------------------------------------------
// HMMA screening kernel: CTA = 128 n x all 1024 codes.
// Prologue stages this CTA's z slice (fp32) into the B region, transposes +
// bf16-splits into A smem (no global zh/zl round trip), and computes exact
// a_n (sequential ascending d, same order as the rel_err=0.0 kernels).
// Mainloop: c = zh*eh (acc Ch) + zh*el + zl*eh (acc Cl), merged in epilogue.
// Per n: track (min1,k1,min2); gap <= DELTA_GAP -> flag for exact fallback.
// smem pitch: 528 B rows (odd x 16B -> ldmatrix conflict-free).
// ---------------------------------------------------------------------------
#define ROWB 528
#define OFF_AH 0
#define OFF_AL 67584            /* 128*528 */
#define OFF_B  135168           /* 2 bufs x (Bh 16896 + Bl 16896); also z stage */
#define OFF_BS 202752           /* 1024 floats */
#define OFF_AS 206848           /* 128 floats */
#define SM_TOTAL 207360
#define PSTG 132                /* z stage pitch in floats (= 528 B) */

extern __shared__ char sm_raw[];

__global__ void __launch_bounds__(256, 1)
k_mma(const float* __restrict__ z) {
    unsigned sb = stu32(sm_raw);
    const int tid = threadIdx.x;
    const int lane = tid & 31, w = tid >> 5;         // w = n-tile 0..7
    const int n0 = blockIdx.x * 128;

    // ---------- Prologue: stage z (fp32) -> split into Ah/Al + exact a_n ----
    float* stg = (float*)(sm_raw + OFF_B);           // [128 d][PSTG] fp32
    const int b = n0 >> 12, hw0 = n0 & 4095;
    const float* zb = z + ((size_t)b << 20) + hw0;   // contiguous 128 n per CTA
    float a_acc = 0.f;

    #pragma unroll
    for (int c = 0; c < 2; ++c) {
        // load 128 d-rows x 128 n fp32 (coalesced; 16B per cp.async)
        for (int i = tid; i < 128 * 32; i += 256) {
            int d = i >> 5, j = i & 31;
            cp16(sb + OFF_B + d * ROWB + j * 16,
                 zb + (size_t)(c * 128 + d) * HW + j * 4);
        }
        cp_commit(); cp_wait0();
        __syncthreads();
        // transpose + split: thread (n = tid>>1, half = tid&1) covers 64 d's
        {
            int nn = tid >> 1, hf = tid & 1;
            unsigned dstA = (unsigned)(nn * ROWB + c * 256 + hf * 128);
            #pragma unroll
            for (int g = 0; g < 8; ++g) {
                __align__(16) __nv_bfloat16 hh[8], ll[8];
                #pragma unroll
                for (int q = 0; q < 8; ++q) {
                    float v = stg[(hf * 64 + g * 8 + q) * PSTG + nn];
                    hh[q] = __float2bfloat16(v);
                    ll[q] = __float2bfloat16(v - __bfloat162float(hh[q]));
                }
                *(uint4*)(sm_raw + OFF_AH + dstA + g * 16) = *(uint4*)hh;
                *(uint4*)(sm_raw + OFF_AL + dstA + g * 16) = *(uint4*)ll;
            }
        }
        // exact a_n partial: thread t<128 owns n=t, ascending d (bit-identical)
        if (tid < 128) {
            #pragma unroll 4
            for (int dl = 0; dl < 128; ++dl) {
                float v = stg[dl * PSTG + tid];
                a_acc = fmaf(v, v, a_acc);
            }
        }
        __syncthreads();                              // stage consumed
    }

    float* bsm  = (float*)(sm_raw + OFF_BS);
    float* asm_ = (float*)(sm_raw + OFF_AS);
    if (tid < 128) { asm_[tid] = a_acc; g_a[n0 + tid] = a_acc; }
    for (int i = tid; i < KCODE; i += 256) bsm[i] = g_b[i];

    // ---------- B pipeline ----------
    auto prefB = [&](int c) {
        unsigned bufh = sb + OFF_B + (c & 1) * 33792;
        const char* eh = (const char*)g_eh;
        const char* el = (const char*)g_el;
        for (int u = tid; u < 32 * 32; u += 256) {
            int r = u >> 5, j = u & 31;
            size_t src = (size_t)(c * 32 + r) * 512 + j * 16;
            unsigned dst = r * ROWB + j * 16;
            cp16(bufh + dst, eh + src);
            cp16(bufh + 16896 + dst, el + src);
        }
    };
    prefB(0); cp_commit();      // G0 = B(0)
    prefB(1); cp_commit();      // G1 = B(1)
    __syncthreads();            // asm_/bsm visible

    // Per-lane ldmatrix addresses (x4 = 4 8x8 matrices)
    const int grp = lane >> 3, ii = lane & 7;
    const unsigned aOff = (unsigned)((w * 16 + ((grp & 1) ? 8 : 0) + ii) * ROWB
                                     + ((grp & 2) ? 16 : 0));
    const unsigned bOff = (unsigned)((((grp >> 1) ? 8 : 0) + ii) * ROWB
                                     + ((grp & 1) ? 16 : 0));

    const float aA = asm_[w * 16 + (lane >> 2)];
    const float aB = asm_[w * 16 + (lane >> 2) + 8];
    float m1A = FLT_MAX, m2A = FLT_MAX, m1B = FLT_MAX, m2B = FLT_MAX;
    int k1A = 0, k1B = 0;

    #define UPD(m1, m2, k1, dv, k) \
        { if ((dv) < (m1)) { (m2) = (m1); (m1) = (dv); (k1) = (k); } \
          else if ((dv) < (m2)) (m2) = (dv); }

    for (int c = 0; c < 32; ++c) {
        if (c == 31) cp_wait0(); else cp_wait1();   // B(c) resident
        __syncthreads();

        unsigned bufh = sb + OFF_B + (c & 1) * 33792;
        unsigned pAh = sb + OFF_AH + aOff;
        unsigned pAl = sb + OFF_AL + aOff;
        unsigned pH0 = bufh + bOff;                  // eh codes 0-15
        unsigned pH1 = bufh + 16 * ROWB + bOff;      // eh codes 16-31
        unsigned pL0 = bufh + 16896 + bOff;          // el codes 0-15
        unsigned pL1 = bufh + 16896 + 16 * ROWB + bOff;

        // Split accumulators: Ch = zh*eh, Cl = zh*el + zl*eh.
        // Reuse distance per tile >= 8 MMA issues -> hides HMMA latency.
        float Ch[4][4], Cl[4][4];
        #pragma unroll
        for (int t = 0; t < 4; ++t)
            #pragma unroll
            for (int q = 0; q < 4; ++q) { Ch[t][q] = 0.f; Cl[t][q] = 0.f; }

        #pragma unroll 4
        for (int s = 0; s < 16; ++s) {
            unsigned Ah[4], Al[4], B0[4], B1[4], B2[4], B3[4];
            ldm4(Ah, pAh); ldm4(Al, pAl);
            ldm4(B0, pH0); ldm4(B1, pH1);
            ldm4(B2, pL0); ldm4(B3, pL1);
            mma16816(Cl[0], Ah, B2[0], B2[1]);   // zh*el
            mma16816(Cl[1], Ah, B2[2], B2[3]);
            mma16816(Cl[2], Ah, B3[0], B3[1]);
            mma16816(Cl[3], Ah, B3[2], B3[3]);
            mma16816(Ch[0], Ah, B0[0], B0[1]);   // zh*eh
            mma16816(Ch[1], Ah, B0[2], B0[3]);
            mma16816(Ch[2], Ah, B1[0], B1[1]);
            mma16816(Ch[3], Ah, B1[2], B1[3]);
            mma16816(Cl[0], Al, B0[0], B0[1]);   // zl*eh
            mma16816(Cl[1], Al, B0[2], B0[3]);
            mma16816(Cl[2], Al, B1[0], B1[1]);
            mma16816(Cl[3], Al, B1[2], B1[3]);
            pAh += 32; pAl += 32; pH0 += 32; pH1 += 32; pL0 += 32; pL1 += 32;
        }

        int kb = c * 32 + (lane & 3) * 2;
        #pragma unroll
        for (int t = 0; t < 4; ++t) {
            int kc = kb + t * 8;
            float b0 = bsm[kc], b1 = bsm[kc + 1];
            float c00 = Ch[t][0] + Cl[t][0];
            float c01 = Ch[t][1] + Cl[t][1];
            float c10 = Ch[t][2] + Cl[t][2];
            float c11 = Ch[t][3] + Cl[t][3];
            float d0 = fmaf(-2.f, c00, aA + b0);
            float d1 = fmaf(-2.f, c01, aA + b1);
            float d2 = fmaf(-2.f, c10, aB + b0);
            float d3 = fmaf(-2.f, c11, aB + b1);
            UPD(m1A, m2A, k1A, d0, kc);
            UPD(m1A, m2A, k1A, d1, kc + 1);
            UPD(m1B, m2B, k1B, d2, kc);
            UPD(m1B, m2B, k1B, d3, kc + 1);
        }

        __syncthreads();                             // all warps done with buf
        if (c + 2 < 32) { prefB(c + 2); cp_commit(); }
    }

    // Reduce across the 4 lanes sharing each row (lex (dv,k); true 2nd-min)
    #pragma unroll
    for (int o = 1; o <= 2; o <<= 1) {
        float om1 = __shfl_xor_sync(0xffffffffu, m1A, o);
        int   ok1 = __shfl_xor_sync(0xffffffffu, k1A, o);
        float om2 = __shfl_xor_sync(0xffffffffu, m2A, o);
        bool take = (om1 < m1A) || (om1 == m1A && ok1 < k1A);
        m2A = fminf(fminf(m2A, om2), take ? m1A : om1);
        if (take) { m1A = om1; k1A = ok1; }

        om1 = __shfl_xor_sync(0xffffffffu, m1B, o);
        ok1 = __shfl_xor_sync(0xffffffffu, k1B, o);
        om2 = __shfl_xor_sync(0xffffffffu, m2B, o);
        take = (om1 < m1B) || (om1 == m1B && ok1 < k1B);
        m2B = fminf(fminf(m2B, om2), take ? m1B : om1);
        if (take) { m1B = om1; k1B = ok1; }
    }
    if ((lane & 3) == 0) {
        int nA = n0 + w * 16 + (lane >> 2);
        if (m2A - m1A > DELTA_GAP) g_idx[nA] = k1A;
        else g_flag[atomicAdd(&g_cnt, 1)] = nA;
        int nB = nA + 8;
        if (m2B - m1B > DELTA_GAP) g_idx[nB] = k1B;
        else g_flag[atomicAdd(&g_cnt, 1)] = nB;
    }
}

// ---------------------------------------------------------------------------
// Exact fallback: bit-identical fp32 full scan for flagged positions only.
// ---------------------------------------------------------------------------
__global__ __launch_bounds__(256)
void k_exact(const float* __restrict__ z, const float* __restrict__ emb) {
    __shared__ float zs[8][257];
    __shared__ float es[32][257];
    __shared__ int ns[8];
    __shared__ float aa[8];
    int tx = threadIdx.x & 31, ty = threadIdx.x >> 5;

    for (int base = blockIdx.x * 8; base < g_cnt; base += gridDim.x * 8) {
        int cnt = g_cnt;
        if (threadIdx.x < 8) {
            int v = (base + threadIdx.x < cnt) ? g_flag[base + threadIdx.x] : -1;
            ns[threadIdx.x] = v;
            aa[threadIdx.x] = (v >= 0) ? g_a[v] : 0.f;
        }
        __syncthreads();
        for (int i = threadIdx.x; i < 8 * 256; i += 256) {
            int sl = i >> 8, d = i & 255;
            int nn = ns[sl];
            zs[sl][d] = (nn >= 0)
                ? z[((size_t)(nn >> 12) << 20) + ((size_t)d << 12) + (nn & 4095)] : 0.f;
        }
        float m1 = FLT_MAX; int k1 = 0;
        for (int c0 = 0; c0 < KCODE; c0 += 32) {
            __syncthreads();
            for (int i = threadIdx.x; i < 32 * 256; i += 256) {
                int r = i >> 8, d = i & 255;
                es[r][d] = emb[(size_t)(c0 + r) * DDIM + d];
            }
            __syncthreads();
            float c = 0.f;
            const float* zr = zs[ty];
            const float* er = es[tx];
            #pragma unroll 4
            for (int d = 0; d < DDIM; ++d) c = fmaf(zr[d], er[d], c);
            float dv = fmaf(-2.0f, c, aa[ty] + g_b[c0 + tx]);
            if (dv < m1) { m1 = dv; k1 = c0 + tx; }
        }
        #pragma unroll
        for (int o = 16; o; o >>= 1) {
            float ov = __shfl_xor_sync(0xffffffffu, m1, o);
            int   ok = __shfl_xor_sync(0xffffffffu, k1, o);
            if (ov < m1 || (ov == m1 && ok < k1)) { m1 = ov; k1 = ok; }
        }
        if (tx == 0 && ns[ty] >= 0) g_idx[ns[ty]] = k1;
        __syncthreads();
    }
}

// ---------------------------------------------------------------------------
// Output + loss (proven in R3)
// ---------------------------------------------------------------------------
__global__ void k_out(const float* __restrict__ z, const float* __restrict__ emb,
                      float* __restrict__ out) {
    const int nitems = NPOS * 64;
    float local = 0.f;
    for (int item = blockIdx.x * blockDim.x + threadIdx.x;
         item < nitems; item += gridDim.x * blockDim.x) {
        int n  = item & (NPOS - 1);
        int dq = item >> 16;
        int idx = __ldg(&g_idx[n]);
        float4 e4 = *(const float4*)(emb + (size_t)idx * DDIM + (dq << 2));
        int b = n >> 12, hw = n & 4095;
        size_t base = ((size_t)b << 20) + ((size_t)(dq << 2) << 12) + hw;
        float ev[4] = {e4.x, e4.y, e4.z, e4.w};
        #pragma unroll
        for (int q = 0; q < 4; ++q) {
            size_t a = base + ((size_t)q << 12);
            float zz = z[a];
            float diff = ev[q] - zz;
            out[a] = zz + diff;
            local = fmaf(diff, diff, local);
        }
    }
    #pragma unroll
    for (int o = 16; o; o >>= 1) local += __shfl_xor_sync(0xffffffffu, local, o);
    __shared__ float ws[32];
    int lane = threadIdx.x & 31, w = threadIdx.x >> 5;
    if (lane == 0) ws[w] = local;
    __syncthreads();
    if (w == 0) {
        float s = (lane < (int)(blockDim.x >> 5)) ? ws[lane] : 0.f;
        #pragma unroll
        for (int o = 16; o; o >>= 1) s += __shfl_xor_sync(0xffffffffu, s, o);
        if (lane == 0) atomicAdd(&g_loss, (double)s);
    }
}

__global__ void k_fin(float* __restrict__ out, long long out_size) {
    int i = blockIdx.x * blockDim.x + threadIdx.x;
    if (i < NPOS && (long long)ZQ_ELEMS + i < out_size)
        out[ZQ_ELEMS + i] = (float)g_idx[i];
    if (i == 0 && (long long)ZQ_ELEMS + NPOS < out_size)
        out[ZQ_ELEMS + NPOS] = (float)(0.25 * g_loss / (double)ZQ_ELEMS);
}

// ---------------------------------------------------------------------------
extern "C" void kernel_launch(void* const* d_in, const int* in_sizes, int n_in,
                              void* d_out, int out_size) {
    const float* z   = (const float*)d_in[0];
    const float* emb = (const float*)d_in[1];
    float* out = (float*)d_out;

    cudaFuncSetAttribute(k_mma, cudaFuncAttributeMaxDynamicSharedMemorySize, SM_TOTAL);

    k_prep<<<KCODE / 8, 256>>>(emb);
    k_mma<<<NPOS / 128, 256, SM_TOTAL>>>(z);
    k_exact<<<256, 256>>>(z, emb);
    k_out<<<2048, 256>>>(z, emb, out);
    k_fin<<<(NPOS + 255) / 256, 256>>>(out, (long long)out_size);
}